// round 12
// baseline (speedup 1.0000x reference)
#include <cuda_runtime.h>
#include <cuda_bf16.h>
#include <math_constants.h>
#include <cstdint>

// Problem: cummax along axis=2 of x[B=8, Tt=128, Ts=128, C=512] fp32.
// out[b,t,j,c] = max_{j'<=j} x[b,t,j',c]
//
// R11 hybrid: R7's proven load path (per-lane LDG.128, ptxas-scoreboarded,
// 1024 CTAs x 128 threads, one (b,t) row per CTA) + BULK STORES ONLY.
// Results stage through smem; every JT=8 j-steps tid0 issues a 16KB
// cp.async.bulk smem->gmem burst (double-buffered). Store stream becomes
// full-line page-sequential bursts; load stream is untouched R7.
// (R10 showed bulk loads strangle the read stream; R3/R9 showed cache
// hints break ptxas batching -- both avoided here.)

constexpr int THREADS = 128;
constexpr int TS      = 128;
constexpr int C4      = 128;           // 512 channels / 4 floats
constexpr int JT      = 8;             // j-steps per store tile
constexpr int NT      = TS / JT;       // 16 tiles
constexpr int TILE_B  = JT * C4 * 16;  // 16384 bytes

__global__ void __launch_bounds__(THREADS) cummax_kernel(
    const float4* __restrict__ in, float4* __restrict__ out)
{
    __shared__ alignas(128) float4 outb[2][JT][THREADS];   // 32 KB

    const int tid = threadIdx.x;
    const int bt  = blockIdx.x;                 // (b,t) row, 0..1023

    const float4* __restrict__ p = in + (size_t)bt * TS * C4 + tid;
    char* gdst = (char*)(out + (size_t)bt * TS * C4);

    float4 m = make_float4(-CUDART_INF_F, -CUDART_INF_F,
                           -CUDART_INF_F, -CUDART_INF_F);

    #pragma unroll 1
    for (int t = 0; t < NT; ++t) {
        const int s = t & 1;

        // Recycle buffer s: the bulk store of tile t-2 must have finished
        // READING smem. Allow 1 outstanding group (store t-1).
        if (t >= 2 && tid == 0)
            asm volatile("cp.async.bulk.wait_group.read 1;" ::: "memory");
        __syncthreads();

        // R7-style compute: 8 plain LDG.128 (ptxas scoreboards/batches),
        // register running max, results to smem (conflict-free 16B/lane).
        #pragma unroll
        for (int u = 0; u < JT; ++u) {
            float4 v = p[(size_t)(t * JT + u) * C4];
            m.x = fmaxf(m.x, v.x);
            m.y = fmaxf(m.y, v.y);
            m.z = fmaxf(m.z, v.z);
            m.w = fmaxf(m.w, v.w);
            outb[s][u][tid] = m;
        }
        __syncthreads();   // all STS of outb[s] complete

        // One thread: 16KB page-sequential bulk store of this tile.
        if (tid == 0) {
            const uint32_t sout =
                (uint32_t)__cvta_generic_to_shared(&outb[s][0][0]);
            asm volatile("fence.proxy.async.shared::cta;" ::: "memory");
            asm volatile(
                "cp.async.bulk.global.shared::cta.bulk_group [%0], [%1], %2;"
                :: "l"(gdst + (size_t)t * TILE_B), "r"(sout), "r"(TILE_B)
                : "memory");
            asm volatile("cp.async.bulk.commit_group;" ::: "memory");
        }
    }

    // Drain outstanding bulk stores before exit.
    if (tid == 0)
        asm volatile("cp.async.bulk.wait_group 0;" ::: "memory");
}

extern "C" void kernel_launch(void* const* d_in, const int* in_sizes, int n_in,
                              void* d_out, int out_size)
{
    const float4* x = (const float4*)d_in[0];
    float4* y = (float4*)d_out;

    // 1024 CTAs = B*Tt rows; 128 threads; 32 KB static smem.
    cummax_kernel<<<1024, THREADS>>>(x, y);
}

// round 13
// speedup vs baseline: 1.0847x; 1.0847x over previous
#include <cuda_runtime.h>
#include <cuda_bf16.h>

// Problem: cummax along axis=2 of x[B=8, Tt=128, Ts=128, C=512] fp32.
// out[b,t,j,c] = max_{j'<=j} x[b,t,j',c]
//
// R12: champion (R7) geometry -- 1024 CTAs x 128 threads, one CTA per (b,t)
// row, plain LDG.128/STG.128, no hints/smem/sync -- with the j-loop FULLY
// unrolled. ~8KB SASS body fits I$ (L0 6KB + L1.5 32KB); ptxas sees the
// whole dependence graph and can batch loads / slot stores into load
// shadows to the limit of its register budget, with zero branch overhead.

static __device__ __forceinline__ float4 f4max(float4 a, float4 b) {
    float4 r;
    r.x = fmaxf(a.x, b.x);
    r.y = fmaxf(a.y, b.y);
    r.z = fmaxf(a.z, b.z);
    r.w = fmaxf(a.w, b.w);
    return r;
}

// One CTA per (b,t) row: 128 threads cover the 128 float4 channel groups.
// Each thread walks j = 0..127 (stride 2KB) with a register running max.
__global__ void __launch_bounds__(128) cummax_kernel(
    const float4* __restrict__ in, float4* __restrict__ out)
{
    constexpr int TS = 128;
    constexpr int C4 = 128;               // 512 channels / 4
    const int bt = blockIdx.x;            // (b,t) row, 0..1023
    const int c4 = threadIdx.x;           // float4 within C, 0..127

    const float4* __restrict__ p = in  + (size_t)bt * TS * C4 + c4;
    float4* __restrict__       q = out + (size_t)bt * TS * C4 + c4;

    float4 m = p[0];
    q[0] = m;

    #pragma unroll
    for (int j = 1; j < TS; ++j) {
        float4 v = p[(size_t)j * C4];
        m = f4max(m, v);
        q[(size_t)j * C4] = m;
    }
}

extern "C" void kernel_launch(void* const* d_in, const int* in_sizes, int n_in,
                              void* d_out, int out_size)
{
    const float4* x = (const float4*)d_in[0];
    float4* y = (float4*)d_out;

    // 1024 CTAs = B*Tt rows; 128 threads = C/4 float4 columns per row.
    cummax_kernel<<<1024, 128>>>(x, y);
}